// round 1
// baseline (speedup 1.0000x reference)
#include <cuda_runtime.h>
#include <math.h>

// ---------------------------------------------------------------------------
// SoftCluster_adaptiveK: gumbel-softmax k selection + k-means++ init +
// soft k-means (beta=1, tau=1, tol=1e-5, 50 iters with early-freeze).
// Output: centers[k,256] then r[80000,k] concatenated (k derived from out_size).
// ---------------------------------------------------------------------------

#define D      256
#define KMAX   6
#define GRID1  148
#define T1     512
#define NW1    (T1 / 32)
#define TOT_W  (GRID1 * NW1)
#define MAX_ITERS 50
#define TOLV   1e-5

// ---- device scratch (static; no allocation in kernel_launch) ----
__device__ float  g_centers[KMAX * D];
__device__ float  g_prev[KMAX * D];
__device__ float  g_csq[KMAX];
__device__ float  g_w[KMAX];
__device__ float  g_P[GRID1 * KMAX * D];   // per-block partial sums of r^T x
__device__ float  g_Pc[GRID1 * KMAX];      // per-block partial colsums of r
__device__ double g_shiftp[KMAX];
__device__ float  g_dmin[131072];          // N = 80000 fits
__device__ int    g_done;
__device__ int    g_maxiters;
__device__ int    g_idx;

__device__ __forceinline__ float dot4(float4 a, float4 b) {
    return a.x * b.x + a.y * b.y + a.z * b.z + a.w * b.w;
}

// ---------------------------------------------------------------------------
// Init: gumbel-softmax weights, done flag, prev=0, pick center 0, csq[0].
// ---------------------------------------------------------------------------
__global__ void k_init(const float* __restrict__ x,
                       const float* __restrict__ logits,
                       const float* __restrict__ gumbel,
                       const float* __restrict__ uinit,
                       const int*   __restrict__ maxit,
                       int N) {
    __shared__ double s_sq[256];
    int tid = threadIdx.x;
    if (tid == 0) {
        g_maxiters = maxit[0];
        g_done = 0;
        float l[KMAX];
        float m = -3.4e38f;
        for (int j = 0; j < KMAX; j++) {
            l[j] = logits[j] + gumbel[j];           // tau = 1
            m = fmaxf(m, l[j]);
        }
        float s = 0.f;
        float e[KMAX];
        for (int j = 0; j < KMAX; j++) { e[j] = expf(l[j] - m); s += e[j]; }
        for (int j = 0; j < KMAX; j++) g_w[j] = e[j] / s;
        // idx0 = min(int(u0 * N), N-1), fp32 multiply then truncate (matches ref)
        float f = uinit[0] * (float)N;
        int idx = (int)f;
        if (idx > N - 1) idx = N - 1;
        if (idx < 0) idx = 0;
        g_idx = idx;
    }
    for (int i = tid; i < KMAX * D; i += blockDim.x) g_prev[i] = 0.f;
    __syncthreads();
    int idx = g_idx;
    float v = x[(size_t)idx * D + tid];
    g_centers[tid] = v;
    s_sq[tid] = (double)v * (double)v;
    __syncthreads();
    for (int s = 128; s; s >>= 1) {
        if (tid < s) s_sq[tid] += s_sq[tid + s];
        __syncthreads();
    }
    if (tid == 0) g_csq[0] = (float)s_sq[0];
}

// ---------------------------------------------------------------------------
// k-means++ pass: update dmin[n] = min(dmin[n], dist(x_n, centers[i-1])).
// ---------------------------------------------------------------------------
__global__ void __launch_bounds__(T1) k_dmin(const float* __restrict__ x, int N, int i) {
    __shared__ float s_c[D];
    __shared__ float s_cs;
    int tid = threadIdx.x;
    if (tid < D) s_c[tid] = g_centers[(i - 1) * D + tid];
    if (tid == 0) s_cs = g_csq[i - 1];
    __syncthreads();
    int lane = tid & 31;
    int warp = tid >> 5;
    int gwarp = blockIdx.x * (blockDim.x >> 5) + warp;
    int tot = gridDim.x * (blockDim.x >> 5);
    const float4* c4 = (const float4*)s_c;
    float4 c0 = c4[lane], c1 = c4[lane + 32];
    for (int row = gwarp; row < N; row += tot) {
        const float4* xr = (const float4*)(x + (size_t)row * D);
        float4 a0 = __ldg(xr + lane);
        float4 a1 = __ldg(xr + lane + 32);
        float dp = dot4(a0, c0) + dot4(a1, c1);
        float xs = dot4(a0, a0) + dot4(a1, a1);
        #pragma unroll
        for (int m = 16; m; m >>= 1) {
            dp += __shfl_xor_sync(0xffffffffu, dp, m);
            xs += __shfl_xor_sync(0xffffffffu, xs, m);
        }
        if (lane == 0) {
            float d = sqrtf(fmaxf(xs + s_cs - 2.f * dp, 1e-12f));
            g_dmin[row] = (i == 1) ? d : fminf(g_dmin[row], d);
        }
    }
}

// ---------------------------------------------------------------------------
// k-means++ select: double-precision scan of dmin, inverse-CDF draw,
// copy chosen row to centers[i], compute csq[i]. Single block, 1024 threads.
// ---------------------------------------------------------------------------
__global__ void k_select(const float* __restrict__ x,
                         const float* __restrict__ uinit,
                         int N, int i) {
    __shared__ double ss[1024];
    __shared__ double s_sq[256];
    __shared__ int s_idx;
    int tid = threadIdx.x;
    int chunk = (N + 1023) >> 10;
    int st = tid * chunk;
    int en = min(st + chunk, N);
    double s = 0.0;
    for (int n = st; n < en; n++) s += (double)g_dmin[n];
    ss[tid] = s;
    __syncthreads();
    // Hillis-Steele inclusive scan
    for (int off = 1; off < 1024; off <<= 1) {
        double v = (tid >= off) ? ss[tid - off] : 0.0;
        __syncthreads();
        ss[tid] += v;
        __syncthreads();
    }
    double total = ss[1023];
    double target = (double)uinit[i] * total;
    if (tid == 0) s_idx = N - 1;
    __syncthreads();
    double incl = ss[tid];
    double E = incl - s;
    if (target > E && target <= incl) {
        double c = E;
        int f = -1;
        for (int n = st; n < en; n++) {
            c += (double)g_dmin[n];
            if (c >= target) { f = n; break; }
        }
        if (f >= 0) s_idx = f;
    }
    __syncthreads();
    int idx = min(s_idx, N - 1);
    if (tid < D) {
        float v = x[(size_t)idx * D + tid];
        g_centers[i * D + tid] = v;
        s_sq[tid] = (double)v * (double)v;
    }
    __syncthreads();
    for (int sft = 128; sft; sft >>= 1) {
        if (tid < sft) s_sq[tid] += s_sq[tid + sft];
        __syncthreads();
    }
    if (tid == 0) g_csq[i] = (float)s_sq[0];
}

// ---------------------------------------------------------------------------
// K1: fused assign + accumulate. Warp-per-row. Single pass over x.
//   d_j = sqrt(max(xsq + csq_j - 2 x.c_j, 1e-12))
//   r_j = w_j exp(dmin - d_j) / sum_l w_l exp(dmin - d_l)   (stable softmax * w)
// Writes r to output; accumulates r^T x and colsum(r) into per-block partials.
// ---------------------------------------------------------------------------
template <int K>
__global__ void __launch_bounds__(T1) k1_assign(const float* __restrict__ x,
                                                float* __restrict__ out_r,
                                                int N, int t) {
    if (g_done || t >= g_maxiters) return;
    __shared__ float s_c[KMAX * D];
    __shared__ float s_acc[KMAX * D];
    __shared__ float s_csq[KMAX];
    __shared__ float s_w[KMAX];
    __shared__ float s_cnt[KMAX];
    int tid = threadIdx.x;
    for (int i = tid; i < K * D; i += T1) { s_c[i] = g_centers[i]; s_acc[i] = 0.f; }
    if (tid < K) { s_csq[tid] = g_csq[tid]; s_w[tid] = g_w[tid]; s_cnt[tid] = 0.f; }
    __syncthreads();

    int lane = tid & 31;
    int warp = tid >> 5;
    int gwarp = blockIdx.x * NW1 + warp;

    float acc[K][8];
    float cnt[K];
    #pragma unroll
    for (int j = 0; j < K; j++) {
        cnt[j] = 0.f;
        #pragma unroll
        for (int u = 0; u < 8; u++) acc[j][u] = 0.f;
    }

    for (int row = gwarp; row < N; row += TOT_W) {
        const float4* xr = (const float4*)(x + (size_t)row * D);
        float4 a0 = __ldg(xr + lane);
        float4 a1 = __ldg(xr + lane + 32);
        float xs = dot4(a0, a0) + dot4(a1, a1);
        float dp[K];
        #pragma unroll
        for (int j = 0; j < K; j++) {
            const float4* cj = (const float4*)(s_c + j * D);
            dp[j] = dot4(a0, cj[lane]) + dot4(a1, cj[lane + 32]);
        }
        #pragma unroll
        for (int m = 16; m; m >>= 1) {
            xs += __shfl_xor_sync(0xffffffffu, xs, m);
            #pragma unroll
            for (int j = 0; j < K; j++) dp[j] += __shfl_xor_sync(0xffffffffu, dp[j], m);
        }
        float dd[K];
        float dmn = 3.4e38f;
        #pragma unroll
        for (int j = 0; j < K; j++) {
            dd[j] = sqrtf(fmaxf(xs + s_csq[j] - 2.f * dp[j], 1e-12f));
            dmn = fminf(dmn, dd[j]);
        }
        float e[K];
        float ssum = 0.f;
        #pragma unroll
        for (int j = 0; j < K; j++) { e[j] = s_w[j] * expf(dmn - dd[j]); ssum += e[j]; }
        float inv = 1.f / ssum;
        float rv = 0.f;
        #pragma unroll
        for (int j = 0; j < K; j++) {
            float rj = e[j] * inv;
            if (lane == j) rv = rj;
            cnt[j] += rj;
            acc[j][0] = fmaf(rj, a0.x, acc[j][0]);
            acc[j][1] = fmaf(rj, a0.y, acc[j][1]);
            acc[j][2] = fmaf(rj, a0.z, acc[j][2]);
            acc[j][3] = fmaf(rj, a0.w, acc[j][3]);
            acc[j][4] = fmaf(rj, a1.x, acc[j][4]);
            acc[j][5] = fmaf(rj, a1.y, acc[j][5]);
            acc[j][6] = fmaf(rj, a1.z, acc[j][6]);
            acc[j][7] = fmaf(rj, a1.w, acc[j][7]);
        }
        if (lane < K) out_r[(size_t)row * K + lane] = rv;
    }

    // deterministic warp->smem combine (fixed order)
    for (int w = 0; w < NW1; w++) {
        if (warp == w) {
            #pragma unroll
            for (int j = 0; j < K; j++) {
                int b = j * D + 4 * lane;
                s_acc[b + 0]   += acc[j][0];
                s_acc[b + 1]   += acc[j][1];
                s_acc[b + 2]   += acc[j][2];
                s_acc[b + 3]   += acc[j][3];
                s_acc[b + 128] += acc[j][4];
                s_acc[b + 129] += acc[j][5];
                s_acc[b + 130] += acc[j][6];
                s_acc[b + 131] += acc[j][7];
            }
            if (lane == 0) {
                #pragma unroll
                for (int j = 0; j < K; j++) s_cnt[j] += cnt[j];
            }
        }
        __syncthreads();
    }
    float* Pb = g_P + (size_t)blockIdx.x * (KMAX * D);
    for (int i = tid; i < K * D; i += T1) Pb[i] = s_acc[i];
    if (tid < K) g_Pc[blockIdx.x * KMAX + tid] = s_cnt[tid];
}

// ---------------------------------------------------------------------------
// K2: one block per cluster j. Reduce partials (double), new_c = sum/cnt,
// write centers/prev, per-cluster shift^2 partial and csq.
// ---------------------------------------------------------------------------
__global__ void k2_update(int k, int t) {
    int j = blockIdx.x;
    if (j >= k) return;
    if (g_done || t >= g_maxiters) return;
    __shared__ double s_red[256];
    __shared__ double s_cnt;
    int tid = threadIdx.x;
    if (tid < 32) {
        double c = 0.0;
        for (int p = tid; p < GRID1; p += 32) c += (double)g_Pc[p * KMAX + j];
        #pragma unroll
        for (int m = 16; m; m >>= 1) c += __shfl_down_sync(0xffffffffu, c, m);
        if (tid == 0) s_cnt = c;
    }
    __syncthreads();
    double cs = s_cnt;
    int e = j * D + tid;
    double sum = 0.0;
    #pragma unroll 4
    for (int p = 0; p < GRID1; p++) sum += (double)g_P[(size_t)p * (KMAX * D) + e];
    float ncf = (float)(sum / cs);
    g_centers[e] = ncf;
    float pv = g_prev[e];
    g_prev[e] = ncf;
    double df = (double)(ncf - pv);
    s_red[tid] = df * df;
    __syncthreads();
    for (int s = 128; s; s >>= 1) {
        if (tid < s) s_red[tid] += s_red[tid + s];
        __syncthreads();
    }
    if (tid == 0) g_shiftp[j] = s_red[0];
    __syncthreads();
    s_red[tid] = (double)ncf * (double)ncf;
    __syncthreads();
    for (int s = 128; s; s >>= 1) {
        if (tid < s) s_red[tid] += s_red[tid + s];
        __syncthreads();
    }
    if (tid == 0) g_csq[j] = (float)s_red[0];
}

// ---------------------------------------------------------------------------
// K3: convergence check. Sets done AFTER centers/r were updated this iter
// (matches the reference scan's use of the pre-update done flag).
// ---------------------------------------------------------------------------
__global__ void k3_check(int k, int t) {
    if (g_done || t >= g_maxiters) return;
    if (threadIdx.x == 0) {
        double s = 0.0;
        for (int j = 0; j < k; j++) s += g_shiftp[j];
        if (sqrt(s) < TOLV) g_done = 1;
    }
}

__global__ void k_copy(float* __restrict__ out_c, int k) {
    for (int i = threadIdx.x; i < k * D; i += blockDim.x) out_c[i] = g_centers[i];
}

// ---------------------------------------------------------------------------
extern "C" void kernel_launch(void* const* d_in, const int* in_sizes, int n_in,
                              void* d_out, int out_size) {
    const float* x      = (const float*)d_in[0];
    const float* logits = (const float*)d_in[1];
    const float* gumbel = (const float*)d_in[2];
    const float* uinit  = (const float*)d_in[3];
    const int*   maxit  = (const int*)d_in[4];

    int N = in_sizes[0] / D;
    int k = out_size / (N + D);     // out = centers[k*D] + r[N*k]
    if (k < 1) k = 1;
    if (k > KMAX) k = KMAX;

    float* out_c = (float*)d_out;
    float* out_r = out_c + (size_t)k * D;

    k_init<<<1, 256>>>(x, logits, gumbel, uinit, maxit, N);
    for (int i = 1; i < k; i++) {
        k_dmin<<<GRID1, T1>>>(x, N, i);
        k_select<<<1, 1024>>>(x, uinit, N, i);
    }
    for (int t = 0; t < MAX_ITERS; t++) {
        switch (k) {
            case 1: k1_assign<1><<<GRID1, T1>>>(x, out_r, N, t); break;
            case 2: k1_assign<2><<<GRID1, T1>>>(x, out_r, N, t); break;
            case 3: k1_assign<3><<<GRID1, T1>>>(x, out_r, N, t); break;
            case 4: k1_assign<4><<<GRID1, T1>>>(x, out_r, N, t); break;
            case 5: k1_assign<5><<<GRID1, T1>>>(x, out_r, N, t); break;
            default: k1_assign<6><<<GRID1, T1>>>(x, out_r, N, t); break;
        }
        k2_update<<<KMAX, 256>>>(k, t);
        k3_check<<<1, 32>>>(k, t);
    }
    k_copy<<<1, 256>>>(out_c, k);
}